// round 14
// baseline (speedup 1.0000x reference)
#include <cuda_runtime.h>
#include <cuda_bf16.h>
#include <cstdint>

#define NN 50000
#define EE 800000
#define FIN 256
#define EMB 128
#define GF 32
#define GG 256
#define NEG_SLOPE 0.2f
#define ETOT (EE + NN)
#define SCAN_B 1024
#define NBLK ((NN + SCAN_B - 1) / SCAN_B)   // 49
#define BM 128
#define BKE 32                               // k-elements per chunk (bf16)
#define AP 20                                // A smem stride in uint32 (16 pairs + pad)
#define BP 132                               // B smem stride in uint32
#define GEMM_BLOCKS ((NN + BM - 1) / BM)     // 391
#define FILL_BLOCKS ((NN + EE + 255) / 256)  // 3321

// ---------------- scratch (device globals; no allocations allowed) -------------
__device__ __nv_bfloat16 g_hb[(size_t)NN * EMB];   // h in bf16 (gather payload)
__device__ float g_x2[(size_t)NN * EMB];           // layer output (fp32)
__device__ float g_as[NN];
__device__ float g_ad[NN];
__device__ int   g_counts[NN];
__device__ int   g_rowptr[NN + 1];
__device__ int   g_bsum[NBLK];
__device__ volatile int g_flag[NBLK];
__device__ int   g_pos[EE];                        // per-edge slot within its dst row
__device__ int   g_csr_src[ETOT];

// ---------------- CSR build ----------------------------------------------------
__global__ void k_zero() {
    int i = blockIdx.x * blockDim.x + threadIdx.x;
    int4* p = (int4*)g_counts;
    if (i < NN / 4) p[i] = make_int4(0, 0, 0, 0);   // NN = 4*12500, exact
    if (i < NBLK) g_flag[i] = 0;
}

// histogram + record each edge's slot within its destination row (4 edges/thread)
__global__ void k_hist(const int* __restrict__ dst) {
    int t = blockIdx.x * blockDim.x + threadIdx.x;
    int e = t * 4;
    if (e < EE) {                                   // EE = 4*200000, exact
        int4 d = *(const int4*)&dst[e];
        int4 p;
        p.x = atomicAdd(&g_counts[d.x], 1);
        p.y = atomicAdd(&g_counts[d.y], 1);
        p.z = atomicAdd(&g_counts[d.z], 1);
        p.w = atomicAdd(&g_counts[d.w], 1);
        *(int4*)&g_pos[e] = p;
    }
}

// single-pass scan: local scan + publish block total + spin on all flags +
// apply global base. 49 blocks, all co-resident -> deadlock-free.
__global__ __launch_bounds__(SCAN_B) void k_scan() {
    __shared__ int warp_sums[32];
    __shared__ int s_base;
    int t = threadIdx.x;
    int lane = t & 31, w = t >> 5;
    int b = blockIdx.x;
    int i = b * SCAN_B + t;
    int v = (i < NN) ? (g_counts[i] + 1) : 0;
    int x = v;
#pragma unroll
    for (int off = 1; off < 32; off <<= 1) {
        int y = __shfl_up_sync(0xFFFFFFFF, x, off);
        if (lane >= off) x += y;
    }
    if (lane == 31) warp_sums[w] = x;
    __syncthreads();
    if (w == 0) {
        int s = warp_sums[lane];
#pragma unroll
        for (int off = 1; off < 32; off <<= 1) {
            int y = __shfl_up_sync(0xFFFFFFFF, s, off);
            if (lane >= off) s += y;
        }
        warp_sums[lane] = s;
    }
    __syncthreads();
    int local_excl = (w > 0 ? warp_sums[w - 1] : 0) + x - v;

    // publish this block's total
    if (t == 0) {
        g_bsum[b] = warp_sums[31];
        __threadfence();
        g_flag[b] = 1;
    }
    // wait for all predecessors (poll one flag per thread)
    if (t < b) {
        while (g_flag[t] == 0) { }
    }
    __syncthreads();
    if (t == 0) {
        int base = 0;
        for (int j = 0; j < b; j++) base += g_bsum[j];
        s_base = base;
    }
    __syncthreads();
    if (i < NN) g_rowptr[i] = s_base + local_excl;
    if (i == 0) g_rowptr[NN] = ETOT;
}

// ---------------- bf16 tensor-core GEMM body (device inline) -------------------
__device__ __forceinline__ uint32_t pack_bf16(float lo, float hi) {
    __nv_bfloat162 t = __floats2bfloat162_rn(lo, hi);
    return *(uint32_t*)&t;
}

__device__ __forceinline__ void mma_bf16(float* c, const uint32_t* a, const uint32_t* b) {
    asm volatile(
        "mma.sync.aligned.m16n8k16.row.col.f32.bf16.bf16.f32 "
        "{%0,%1,%2,%3}, {%4,%5,%6,%7}, {%8,%9}, {%0,%1,%2,%3};\n"
        : "+f"(c[0]), "+f"(c[1]), "+f"(c[2]), "+f"(c[3])
        : "r"(a[0]), "r"(a[1]), "r"(a[2]), "r"(a[3]), "r"(b[0]), "r"(b[1]));
}

__device__ __forceinline__ void gemm_body(int m0,
                                          const float* __restrict__ A,
                                          const float* __restrict__ B,
                                          __nv_bfloat16* __restrict__ C,
                                          const float* __restrict__ a_src,
                                          const float* __restrict__ a_dst,
                                          int M, int K) {
    __shared__ uint32_t As[2][BM][AP];
    __shared__ uint32_t Bs[2][BKE / 2][BP];
    __shared__ float s_av[2][128];
    __shared__ float s_pa[128][2];
    int tid = threadIdx.x;
    int lane = tid & 31, wid = tid >> 5;
    int wm = wid >> 2;
    int wn = wid & 3;
    int g = lane >> 2, kk = lane & 3;

    if (tid < 128) {
        s_av[0][tid] = a_src[tid];
        s_pa[tid][0] = 0.f;
        s_pa[tid][1] = 0.f;
    } else {
        s_av[1][tid - 128] = a_dst[tid - 128];
    }

    int arow = tid >> 2;
    int apc = (tid & 3) << 2;
    int ak = apc << 1;
    int bk2 = tid >> 5;
    int bcol = (tid & 31) << 2;

    float c[4][4][4];
#pragma unroll
    for (int mt = 0; mt < 4; mt++)
#pragma unroll
        for (int nt = 0; nt < 4; nt++)
#pragma unroll
            for (int i = 0; i < 4; i++) c[mt][nt][i] = 0.f;

    float4 ra[2][2], rb[2][2];
    const int nch = K / BKE;

#pragma unroll
    for (int r = 0; r < 2; r++) {
        int row = m0 + arow + r * 64;
        if (row < M) {
            ra[r][0] = *(const float4*)&A[(size_t)row * K + ak];
            ra[r][1] = *(const float4*)&A[(size_t)row * K + ak + 4];
        } else {
            ra[r][0] = make_float4(0, 0, 0, 0);
            ra[r][1] = make_float4(0, 0, 0, 0);
        }
    }
#pragma unroll
    for (int s = 0; s < 2; s++) {
        int krow = (bk2 + s * 8) * 2;
        rb[s][0] = *(const float4*)&B[(size_t)krow * 128 + bcol];
        rb[s][1] = *(const float4*)&B[(size_t)(krow + 1) * 128 + bcol];
    }
    {
#pragma unroll
        for (int r = 0; r < 2; r++) {
            uint32_t* pa = &As[0][arow + r * 64][apc];
            pa[0] = pack_bf16(ra[r][0].x, ra[r][0].y);
            pa[1] = pack_bf16(ra[r][0].z, ra[r][0].w);
            pa[2] = pack_bf16(ra[r][1].x, ra[r][1].y);
            pa[3] = pack_bf16(ra[r][1].z, ra[r][1].w);
        }
#pragma unroll
        for (int s = 0; s < 2; s++) {
            uint32_t* pb = &Bs[0][bk2 + s * 8][bcol];
            pb[0] = pack_bf16(rb[s][0].x, rb[s][1].x);
            pb[1] = pack_bf16(rb[s][0].y, rb[s][1].y);
            pb[2] = pack_bf16(rb[s][0].z, rb[s][1].z);
            pb[3] = pack_bf16(rb[s][0].w, rb[s][1].w);
        }
    }
    __syncthreads();

    for (int c0 = 0; c0 < nch; c0++) {
        int cur = c0 & 1;
        if (c0 + 1 < nch) {
            int k0 = (c0 + 1) * BKE;
#pragma unroll
            for (int r = 0; r < 2; r++) {
                int row = m0 + arow + r * 64;
                if (row < M) {
                    ra[r][0] = *(const float4*)&A[(size_t)row * K + k0 + ak];
                    ra[r][1] = *(const float4*)&A[(size_t)row * K + k0 + ak + 4];
                } else {
                    ra[r][0] = make_float4(0, 0, 0, 0);
                    ra[r][1] = make_float4(0, 0, 0, 0);
                }
            }
#pragma unroll
            for (int s = 0; s < 2; s++) {
                int krow = k0 + (bk2 + s * 8) * 2;
                rb[s][0] = *(const float4*)&B[(size_t)krow * 128 + bcol];
                rb[s][1] = *(const float4*)&B[(size_t)(krow + 1) * 128 + bcol];
            }
        }
#pragma unroll
        for (int ks = 0; ks < 2; ks++) {
            int kb = ks * 8;
            uint32_t af[4][4], bf[4][2];
#pragma unroll
            for (int mt = 0; mt < 4; mt++) {
                int row = wm * 64 + mt * 16 + g;
                af[mt][0] = As[cur][row][kb + kk];
                af[mt][1] = As[cur][row + 8][kb + kk];
                af[mt][2] = As[cur][row][kb + kk + 4];
                af[mt][3] = As[cur][row + 8][kb + kk + 4];
            }
#pragma unroll
            for (int nt = 0; nt < 4; nt++) {
                int col = wn * 32 + nt * 8 + g;
                bf[nt][0] = Bs[cur][kb + kk][col];
                bf[nt][1] = Bs[cur][kb + kk + 4][col];
            }
#pragma unroll
            for (int mt = 0; mt < 4; mt++)
#pragma unroll
                for (int nt = 0; nt < 4; nt++)
                    mma_bf16(c[mt][nt], af[mt], bf[nt]);
        }
        if (c0 + 1 < nch) {
            int nb = (c0 + 1) & 1;
#pragma unroll
            for (int r = 0; r < 2; r++) {
                uint32_t* pa = &As[nb][arow + r * 64][apc];
                pa[0] = pack_bf16(ra[r][0].x, ra[r][0].y);
                pa[1] = pack_bf16(ra[r][0].z, ra[r][0].w);
                pa[2] = pack_bf16(ra[r][1].x, ra[r][1].y);
                pa[3] = pack_bf16(ra[r][1].z, ra[r][1].w);
            }
#pragma unroll
            for (int s = 0; s < 2; s++) {
                uint32_t* pb = &Bs[nb][bk2 + s * 8][bcol];
                pb[0] = pack_bf16(rb[s][0].x, rb[s][1].x);
                pb[1] = pack_bf16(rb[s][0].y, rb[s][1].y);
                pb[2] = pack_bf16(rb[s][0].z, rb[s][1].z);
                pb[3] = pack_bf16(rb[s][0].w, rb[s][1].w);
            }
            __syncthreads();
        }
    }

    // epilogue: store C (bf16) + fused attention-dot partials (fp32)
#pragma unroll
    for (int mt = 0; mt < 4; mt++) {
        int row = m0 + wm * 64 + mt * 16 + g;
#pragma unroll
        for (int nt = 0; nt < 4; nt++) {
            int col = wn * 32 + nt * 8 + kk * 2;
            if (row < M)
                *(__nv_bfloat162*)&C[(size_t)row * 128 + col] =
                    __floats2bfloat162_rn(c[mt][nt][0], c[mt][nt][1]);
            if (row + 8 < M)
                *(__nv_bfloat162*)&C[(size_t)(row + 8) * 128 + col] =
                    __floats2bfloat162_rn(c[mt][nt][2], c[mt][nt][3]);
        }
#pragma unroll
        for (int half = 0; half < 2; half++) {
            float ps = 0.f, pd = 0.f;
#pragma unroll
            for (int nt = 0; nt < 4; nt++) {
#pragma unroll
                for (int i = 0; i < 2; i++) {
                    int col = wn * 32 + nt * 8 + kk * 2 + i;
                    float v = c[mt][nt][half * 2 + i];
                    ps += v * s_av[0][col];
                    pd += v * s_av[1][col];
                }
            }
            ps += __shfl_xor_sync(0xFFFFFFFF, ps, 1);
            ps += __shfl_xor_sync(0xFFFFFFFF, ps, 2);
            pd += __shfl_xor_sync(0xFFFFFFFF, pd, 1);
            pd += __shfl_xor_sync(0xFFFFFFFF, pd, 2);
            if (kk == 0) {
                int lr = wm * 64 + mt * 16 + g + half * 8;
                atomicAdd(&s_pa[lr][0], ps);
                atomicAdd(&s_pa[lr][1], pd);
            }
        }
    }
    __syncthreads();
    if (tid < 128 && m0 + tid < M) {
        g_as[m0 + tid] = s_pa[tid][0];
        g_ad[m0 + tid] = s_pa[tid][1];
    }
}

// plain GEMM kernel (layer 2)
__global__ __launch_bounds__(256) void k_gemm_tc(const float* __restrict__ A,
                                                 const float* __restrict__ B,
                                                 __nv_bfloat16* __restrict__ C,
                                                 const float* __restrict__ a_src,
                                                 const float* __restrict__ a_dst,
                                                 int M, int K) {
    gemm_body(blockIdx.x * BM, A, B, C, a_src, a_dst, M, K);
}

// fused GEMM1 + CSR fill (block-partitioned; fill has no atomics thanks to g_pos)
__global__ __launch_bounds__(256) void k_gemm_fill(const float* __restrict__ A,
                                                   const float* __restrict__ B,
                                                   __nv_bfloat16* __restrict__ C,
                                                   const float* __restrict__ a_src,
                                                   const float* __restrict__ a_dst,
                                                   int M, int K,
                                                   const int* __restrict__ src,
                                                   const int* __restrict__ dst) {
    if (blockIdx.x < GEMM_BLOCKS) {
        gemm_body(blockIdx.x * BM, A, B, C, a_src, a_dst, M, K);
    } else {
        int t = (blockIdx.x - GEMM_BLOCKS) * blockDim.x + threadIdx.x;
        if (t < NN) {
            g_csr_src[g_rowptr[t]] = t;                       // self loop first
        } else if (t < NN + EE) {
            int e = t - NN;
            int d = dst[e];
            g_csr_src[g_rowptr[d] + 1 + g_pos[e]] = src[e];   // pure store
        }
    }
}

__device__ __forceinline__ float lrelu(float x) {
    return x > 0.f ? x : NEG_SLOPE * x;
}

// ---------------- single-pass aggregation, smem-staged weights -----------------
__global__ __launch_bounds__(256) void k_aggregate(const __nv_bfloat16* __restrict__ h,
                                                   const float* __restrict__ b,
                                                   float* __restrict__ out) {
    __shared__ int   sh_s[8][32];
    __shared__ float sh_w[8][32];
    int warp = threadIdx.x >> 5;
    int lane = threadIdx.x & 31;
    int v = (blockIdx.x * blockDim.x + threadIdx.x) >> 5;
    if (v >= NN) return;
    int beg = g_rowptr[v];
    int end = g_rowptr[v + 1];
    float adv = g_ad[v];

    float4 acc = make_float4(0.f, 0.f, 0.f, 0.f);
    float den_p = 0.f;
    for (int c0 = beg; c0 < end; c0 += 32) {
        int n = min(32, end - c0);
        int s = 0;
        float w = 0.f;
        if (lane < n) {
            s = g_csr_src[c0 + lane];
            w = __expf(lrelu(__ldg(&g_as[s]) + adv));
        }
        sh_s[warp][lane] = s;
        sh_w[warp][lane] = w;
        __syncwarp();
        den_p += w;
#pragma unroll 4
        for (int j = 0; j < n; j++) {
            float wb = sh_w[warp][j];
            int sb = sh_s[warp][j];
            uint2 u = *(const uint2*)&h[(size_t)sb * 128 + lane * 4];
            float2 f0 = __bfloat1622float2(*(__nv_bfloat162*)&u.x);
            float2 f1 = __bfloat1622float2(*(__nv_bfloat162*)&u.y);
            acc.x += wb * f0.x;
            acc.y += wb * f0.y;
            acc.z += wb * f1.x;
            acc.w += wb * f1.y;
        }
        __syncwarp();
    }
#pragma unroll
    for (int off = 16; off > 0; off >>= 1)
        den_p += __shfl_xor_sync(0xFFFFFFFF, den_p, off);

    float inv = 1.f / den_p;
    float4 b4 = *(const float4*)&b[lane * 4];
    float4 o = make_float4(acc.x * inv + b4.x, acc.y * inv + b4.y,
                           acc.z * inv + b4.z, acc.w * inv + b4.w);
    *(float4*)&out[(size_t)v * 128 + lane * 4] = o;
}

// ---------------- fused pooling + g-feature + head (block per graph) -----------
__device__ __forceinline__ int lower_bound_i(const int* a, int n, int key) {
    int lo = 0, hi = n;
    while (lo < hi) {
        int mid = (lo + hi) >> 1;
        if (a[mid] < key) lo = mid + 1;
        else hi = mid;
    }
    return lo;
}

__global__ __launch_bounds__(128) void k_poolhead(const float* __restrict__ x,
                                                  const int* __restrict__ batch,
                                                  const float* __restrict__ gfeat,
                                                  const float* __restrict__ Wg,
                                                  const float* __restrict__ bg,
                                                  const float* __restrict__ Wo,
                                                  const float* __restrict__ bo,
                                                  float* __restrict__ out) {
    int g = blockIdx.x;
    int f = threadIdx.x;
    __shared__ int s_lo, s_hi;
    __shared__ float sgf[GF];
    __shared__ float red[2][4];
    if (f == 0) s_lo = lower_bound_i(batch, NN, g);
    if (f == 1) s_hi = lower_bound_i(batch, NN, g + 1);
    if (f >= 64 && f < 64 + GF) sgf[f - 64] = gfeat[g * GF + (f - 64)];
    __syncthreads();
    int lo = s_lo, hi = s_hi;

    float s = 0.f, mx = -1e30f;
    for (int i = lo; i < hi; i++) {
        float v = x[(size_t)i * 128 + f];
        s += v;
        mx = fmaxf(mx, v);
    }
    int cnt = hi - lo;
    float mean = s / (float)max(cnt, 1);
    mx = (cnt > 0) ? mx : 0.f;

    float gft = bg[f];
#pragma unroll
    for (int k = 0; k < GF; k++)
        gft += sgf[k] * Wg[k * EMB + f];

    float c0 = mean * Wo[f * 2 + 0] + mx * Wo[(128 + f) * 2 + 0] + gft * Wo[(256 + f) * 2 + 0];
    float c1 = mean * Wo[f * 2 + 1] + mx * Wo[(128 + f) * 2 + 1] + gft * Wo[(256 + f) * 2 + 1];
#pragma unroll
    for (int off = 16; off > 0; off >>= 1) {
        c0 += __shfl_xor_sync(0xFFFFFFFF, c0, off);
        c1 += __shfl_xor_sync(0xFFFFFFFF, c1, off);
    }
    int lane = f & 31, w = f >> 5;
    if (lane == 0) { red[0][w] = c0; red[1][w] = c1; }
    __syncthreads();
    if (f == 0) {
        float l0 = red[0][0] + red[0][1] + red[0][2] + red[0][3] + bo[0];
        float l1 = red[1][0] + red[1][1] + red[1][2] + red[1][3] + bo[1];
        float m = fmaxf(l0, l1);
        float lse = m + logf(expf(l0 - m) + expf(l1 - m));
        out[g * 2 + 0] = l0 - lse;
        out[g * 2 + 1] = l1 - lse;
    }
}

// ---------------- launch --------------------------------------------------------
extern "C" void kernel_launch(void* const* d_in, const int* in_sizes, int n_in,
                              void* d_out, int out_size) {
    const float* x      = (const float*)d_in[0];
    const int*   edges  = (const int*)d_in[1];
    const int*   batch  = (const int*)d_in[2];
    const float* gfeat  = (const float*)d_in[3];
    const float* W1     = (const float*)d_in[4];
    const float* a1s    = (const float*)d_in[5];
    const float* a1d    = (const float*)d_in[6];
    const float* b1     = (const float*)d_in[7];
    const float* W2     = (const float*)d_in[8];
    const float* a2s    = (const float*)d_in[9];
    const float* a2d    = (const float*)d_in[10];
    const float* b2     = (const float*)d_in[11];
    const float* Wg     = (const float*)d_in[12];
    const float* bg     = (const float*)d_in[13];
    const float* Wo     = (const float*)d_in[14];
    const float* bo     = (const float*)d_in[15];
    float* out = (float*)d_out;

    const int* src = edges;
    const int* dst = edges + EE;

    __nv_bfloat16* d_hb; cudaGetSymbolAddress((void**)&d_hb, g_hb);
    float* d_x2; cudaGetSymbolAddress((void**)&d_x2, g_x2);

    // CSR prefix (zero -> hist(+pos) -> single-pass scan)
    k_zero<<<(NN / 4 + 255) / 256, 256>>>();
    k_hist<<<(EE / 4 + 255) / 256, 256>>>(dst);
    k_scan<<<NBLK, SCAN_B>>>();

    int warp_blocks = (NN * 32 + 255) / 256;

    // fused: GEMM1 (h, as, ad) + CSR fill (atomic-free, hidden under GEMM)
    k_gemm_fill<<<GEMM_BLOCKS + FILL_BLOCKS, 256>>>(x, W1, d_hb, a1s, a1d, NN, FIN, src, dst);
    k_aggregate<<<warp_blocks, 256>>>(d_hb, b1, d_x2);

    // layer 2
    k_gemm_tc<<<GEMM_BLOCKS, 256>>>(d_x2, W2, d_hb, a2s, a2d, NN, EMB);
    k_aggregate<<<warp_blocks, 256>>>(d_hb, b2, d_x2);

    // fused pooling + g-feature + head
    k_poolhead<<<GG, 128>>>(d_x2, batch, gfeat, Wg, bg, Wo, bo, out);
}